// round 14
// baseline (speedup 1.0000x reference)
#include <cuda_runtime.h>
#include <cstddef>
#include <cstring>

#define Bv 32
#define Tv 512
#define Cv 8
#define Hv 256
#define Gv 1024

// ---------------- scratch (device globals: allocation-free) ----------------
__device__ float g_h1[(size_t)Tv * Cv * Hv * Bv];        // layer1 hidden, [T][C][H][B]
__device__ float g_xp2[(size_t)Tv * Cv * 16 * Bv * 64];  // layer2 input proj, [T][C][rank][B][64row]
__device__ float g_hbuf[2 * Cv * Hv * Bv];               // h exchange, [2][C][H][B]
__device__ float g_opart[(size_t)Tv * Cv * 16 * Bv];     // head partials [T][C][rank][B]
__device__ unsigned g_cnt[Cv];                           // barrier counters (zero-init)
__device__ unsigned g_sense[Cv];                         // barrier sense (zero-init)

// ---------------- math helpers ----------------
__device__ __forceinline__ float sig_(float x) {
    return __fdividef(1.0f, 1.0f + __expf(-x));
}
__device__ __forceinline__ float tanh_(float x) {
    float ax = fabsf(x);
    float e  = __expf(-2.0f * ax);
    float t  = __fdividef(1.0f - e, 1.0f + e);
    return copysignf(t, x);
}
__device__ __forceinline__ float2 u2f(unsigned long long u) {
    float2 f; memcpy(&f, &u, 8); return f;
}

// packed fp32x2 FMA (FFMA2) and operand duplication
#define FMA2(acc, h, w) asm("fma.rn.f32x2 %0, %1, %2, %0;" : "+l"(acc) : "l"(h), "l"(w))
#define PACK2(d, s)     asm("mov.b64 %0, {%1, %1};" : "=l"(d) : "f"(s))

// cp.async helpers
__device__ __forceinline__ unsigned smem_u32(const void* p) {
    unsigned r;
    asm("{ .reg .u64 t; cvta.to.shared.u64 t, %1; cvt.u32.u64 %0, t; }" : "=r"(r) : "l"(p));
    return r;
}
__device__ __forceinline__ void cp16(unsigned s, const void* g) {
    asm volatile("cp.async.cg.shared.global [%0], [%1], 16;" :: "r"(s), "l"(g));
}
#define CP_COMMIT() asm volatile("cp.async.commit_group;" ::: "memory")
#define CP_WAIT0()  asm volatile("cp.async.wait_group 0;" ::: "memory")

// per-channel sense-reversing barrier (R7/R13-proven, BYTE-IDENTICAL)
__device__ __forceinline__ void chan_barrier(int c, unsigned &lsense) {
    __syncthreads();
    if (threadIdx.x == 0) {
        __threadfence();
        unsigned a = atomicAdd(&g_cnt[c], 1u);
        if (a == 15u) {
            *(volatile unsigned*)&g_cnt[c] = 0u;
            __threadfence();
            *(volatile unsigned*)&g_sense[c] = lsense ^ 1u;
        } else {
            while (*(volatile unsigned*)&g_sense[c] == lsense) { __nanosleep(20); }
            __threadfence();
        }
    }
    lsense ^= 1u;
    __syncthreads();
}

// ---------------- lstm smem layout (floats) ----------------
// Whh_s [256][64] : 16384 | h_s [256][32] : 8192
// gsm/part0/part1 [32][66] : 2112 each
// c_s 512, bsum 64, wih1s 64, xs 32, wlin16 16, xp2_s 2x[32][68]=4352
#define GSTR 66
#define SM_FLOATS (16384 + 8192 + 3 * 2112 + 512 + 64 + 64 + 32 + 16 + 4352)
#define SM_BYTES  (SM_FLOATS * 4)   // 143,808 B

// ---------------- xp2 GEMM smem ----------------
#define XP2_SM_BYTES ((16384 + 4 * 8192) * 4)   // 196,608 B

// ================= xp2 GEMM: xp2[t][c][rank][b][row] = h1[t] @ Wih2^T =================
__global__ __launch_bounds__(512, 1)
void xp2_kernel(const float* __restrict__ Wih2)   // [C][G][H]
{
    extern __shared__ float sm[];
    float* W_s = sm;            // [256][64] k-major
    float* h1s = sm + 16384;    // [4][256][32]

    const int tid   = threadIdx.x;
    const int rank  = blockIdx.x;
    const int c     = blockIdx.y;
    const int t0    = blockIdx.z * 4;
    const int jbase = rank << 4;

    const int rp  = tid & 31;          // row-pair -> rows 2rp, 2rp+1
    const int oct = (tid >> 5) & 3;    // batch octet
    const int tq  = tid >> 7;          // timestep within chunk

    // stage W slice (k-major, same transform as lstm kernel)
    for (int idx = tid; idx < 64 * Hv; idx += 512) {
        int k = idx >> 6, r = idx & 63;
        int g = r >> 4, jl = r & 15;
        size_t grow = (size_t)c * Gv + g * Hv + (jbase + jl);
        W_s[k * 64 + r] = __ldg(&Wih2[grow * Hv + k]);
    }
    // stage h1 for 4 timesteps (straight copy, [k][b] layout preserved)
    {
        const unsigned dst0 = smem_u32(h1s) + (unsigned)tid * 16u;
        #pragma unroll
        for (int i = 0; i < 4; ++i) {
            const float* src = g_h1 + ((size_t)(t0 + i) * Cv + c) * (Hv * Bv) + tid * 4;
            #pragma unroll
            for (int q = 0; q < 4; ++q)
                cp16(dst0 + (unsigned)(i * 8192 + q * 2048) * 4u, src + q * 2048);
        }
        CP_COMMIT(); CP_WAIT0();
    }
    __syncthreads();

    // matvec: rows {2rp,2rp+1} x batches oct*8..+7, full K=256, timestep t0+tq
    unsigned long long A[8];
    #pragma unroll
    for (int i = 0; i < 8; ++i) A[i] = 0ull;
    {
        const float* wh  = W_s + 2 * rp;
        const float* hpp = h1s + tq * 8192 + oct * 8;
        #pragma unroll 4
        for (int kk = 0; kk < Hv; ++kk) {
            float2 wv = *(const float2*)wh;  wh += 64;
            unsigned long long w0, w1;
            PACK2(w0, wv.x); PACK2(w1, wv.y);
            ulonglong2 ha = *(const ulonglong2*)hpp;
            ulonglong2 hb = *(const ulonglong2*)(hpp + 4);  hpp += 32;
            FMA2(A[0], ha.x, w0); FMA2(A[1], ha.y, w0);
            FMA2(A[2], hb.x, w0); FMA2(A[3], hb.y, w0);
            FMA2(A[4], ha.x, w1); FMA2(A[5], ha.y, w1);
            FMA2(A[6], hb.x, w1); FMA2(A[7], hb.y, w1);
        }
    }
    // write xp2: [b][row] slice, float2 spans rows (2rp, 2rp+1), coalesced per p
    float* dst = g_xp2 + (((size_t)(t0 + tq) * Cv + c) * 16 + rank) * (Bv * 64);
    #pragma unroll
    for (int p = 0; p < 4; ++p) {
        int b = oct * 8 + 2 * p;
        float2 re = u2f(A[p]);       // batches (b, b+1), row 2rp
        float2 ro = u2f(A[4 + p]);   // row 2rp+1
        *(float2*)(dst + b * 64 + 2 * rp)       = make_float2(re.x, ro.x);
        *(float2*)(dst + (b + 1) * 64 + 2 * rp) = make_float2(re.y, ro.y);
    }
}

// ================= recurrent LSTM layer (both layers: Whh-only matvec) =================
template <int LAYER>
__global__ __launch_bounds__(512, 1)
void lstm_kernel(const float* __restrict__ x,
                 const float* __restrict__ Wih,   // L1 only: [C][G][1]
                 const float* __restrict__ Whh,   // [C][G][H]
                 const float* __restrict__ bih,   // [C][G]
                 const float* __restrict__ bhh,   // [C][G]
                 const float* __restrict__ Wlin)  // [C][H]  (L2)
{
    extern __shared__ float sm[];
    float* Whh_s  = sm;
    float* h_s    = Whh_s + 16384;
    float* gsm    = h_s   + 8192;
    float* part0  = gsm   + Bv * GSTR;
    float* part1  = part0 + Bv * GSTR;
    float* c_s    = part1 + Bv * GSTR;
    float* bsum   = c_s   + 512;
    float* wih1s  = bsum  + 64;
    float* xs     = wih1s + 64;
    float* wlin16 = xs    + 32;
    float* xp2_s  = wlin16 + 16;      // 2 x [32][68]

    const int tid   = threadIdx.x;
    const int c     = blockIdx.x >> 4;
    const int rank  = blockIdx.x & 15;
    const int jbase = rank << 4;

    // compute decomposition (R7-proven): warp = 32 row-pairs, fixed (oct, kq)
    const int rp  = tid & 31;
    const int oct = (tid >> 5) & 3;
    const int kq  = tid >> 7;

    // activation decomposition (coalesced global stores)
    const int ab = tid & 31;           // batch = lane
    const int aj = tid >> 5;           // local hidden idx 0..15

    // ---- init: weights k-major, biases, zero state ----
    for (int idx = tid; idx < 64 * Hv; idx += 512) {
        int k  = idx >> 6;
        int r  = idx & 63;
        int g  = r >> 4;
        int jl = r & 15;
        size_t grow = (size_t)c * Gv + g * Hv + (jbase + jl);
        Whh_s[k * 64 + r] = Whh[grow * Hv + k];
    }
    if (tid < 64) {
        int g = tid >> 4, jl = tid & 15;
        size_t gi = (size_t)c * Gv + g * Hv + (jbase + jl);
        bsum[tid] = bih[gi] + bhh[gi];
        if (LAYER == 1) wih1s[tid] = Wih[gi];
    }
    if (LAYER == 2 && tid < 16) wlin16[tid] = Wlin[c * Hv + jbase + tid];
    for (int i = tid; i < Hv * Bv; i += 512) h_s[i] = 0.0f;
    c_s[tid] = 0.0f;
    __syncthreads();

    // xp2 staging addresses (L2): thread copies one 16B chunk per step
    const unsigned xp2s_base = smem_u32(xp2_s);
    const unsigned soff = (unsigned)(((tid >> 4) * 68 + (tid & 15) * 4) * 4);
    const size_t xp2cr = ((size_t)c * 16 + rank) * (Bv * 64);

    // ---- prefetch step-0 inputs ----
    float xr = 0.0f;
    if (LAYER == 2) {
        const float* src = g_xp2 + (size_t)0 * (Cv * 16 * Bv * 64) + xp2cr + tid * 4;
        cp16(xp2s_base + soff, src);
        CP_COMMIT();
    } else {
        if (tid < Bv) xr = __ldg(&x[(size_t)tid * Tv * Cv + c]);
    }

    unsigned lsense = 0;

    for (int t = 0; t < Tv; ++t) {
        // ---- inputs ready ----
        if (LAYER == 2) {
            CP_WAIT0();
        } else {
            if (tid < Bv) xs[tid] = xr;
        }
        __syncthreads();   // h_s reload (prev step) + staged inputs visible

        // ---- gate mat-vec: rows {2rp,2rp+1} x batches oct*8..+7 over k-quarter ----
        unsigned long long A[8];
        #pragma unroll
        for (int i = 0; i < 8; ++i) A[i] = 0ull;
        {
            const float* wh  = Whh_s + kq * 64 * 64 + 2 * rp;
            const float* hpp = h_s   + kq * 64 * 32 + oct * 8;

            #pragma unroll 4
            for (int kk = 0; kk < 64; ++kk) {
                float2 wv = *(const float2*)wh;  wh += 64;
                unsigned long long w0, w1;
                PACK2(w0, wv.x); PACK2(w1, wv.y);
                ulonglong2 ha = *(const ulonglong2*)hpp;
                ulonglong2 hb = *(const ulonglong2*)(hpp + 4);  hpp += 32;
                FMA2(A[0], ha.x, w0); FMA2(A[1], ha.y, w0);
                FMA2(A[2], hb.x, w0); FMA2(A[3], hb.y, w0);
                FMA2(A[4], ha.x, w1); FMA2(A[5], ha.y, w1);
                FMA2(A[6], hb.x, w1); FMA2(A[7], hb.y, w1);
            }
        }
        float2 R[8];
        #pragma unroll
        for (int i = 0; i < 8; ++i) R[i] = u2f(A[i]);

        // ---- cross-kq reduction: kq 0->gsm, 2->part0, 3->part1; kq1 combines ----
        {
            float* dst = (kq == 0) ? gsm : (kq == 2) ? part0 : (kq == 3) ? part1 : (float*)0;
            if (dst) {
                #pragma unroll
                for (int p = 0; p < 4; ++p) {
                    int b = oct * 8 + 2 * p;
                    *(float2*)(dst + b * GSTR + 2 * rp)       = make_float2(R[p].x, R[4 + p].x);
                    *(float2*)(dst + (b + 1) * GSTR + 2 * rp) = make_float2(R[p].y, R[4 + p].y);
                }
            }
        }
        __syncthreads();   // sync1

        // ---- prefetch next step's xp2 / x ----
        if (LAYER == 2) {
            if (t + 1 < Tv) {
                const float* src = g_xp2 + (size_t)(t + 1) * (Cv * 16 * Bv * 64) + xp2cr + tid * 4;
                cp16(xp2s_base + (unsigned)(((t + 1) & 1) * 2176 * 4) + soff, src);
                CP_COMMIT();
            }
        } else {
            if (tid < Bv && t + 1 < Tv)
                xr = __ldg(&x[(size_t)tid * Tv * Cv + (t + 1) * Cv + c]);
        }

        if (kq == 1) {
            #pragma unroll
            for (int p = 0; p < 4; ++p) {
                int b = oct * 8 + 2 * p;
                float2* g0 = (float2*)(gsm + b * GSTR + 2 * rp);
                float2* g1 = (float2*)(gsm + (b + 1) * GSTR + 2 * rp);
                float2 p00 = *(float2*)(part0 + b * GSTR + 2 * rp);
                float2 p01 = *(float2*)(part0 + (b + 1) * GSTR + 2 * rp);
                float2 p10 = *(float2*)(part1 + b * GSTR + 2 * rp);
                float2 p11 = *(float2*)(part1 + (b + 1) * GSTR + 2 * rp);
                float2 a = *g0, bb = *g1;
                a.x  += p00.x + p10.x + R[p].x;
                a.y  += p00.y + p10.y + R[4 + p].x;
                bb.x += p01.x + p11.x + R[p].y;
                bb.y += p01.y + p11.y + R[4 + p].y;
                *g0 = a; *g1 = bb;
            }
        }
        __syncthreads();   // sync2: gsm final

        // ---- activations + state update: thread -> (b = lane, j = warp) ----
        {
            const float* gr = gsm + ab * GSTR;
            float vi = gr[      aj] + bsum[      aj];
            float vf = gr[16 + aj] + bsum[16 + aj];
            float vg = gr[32 + aj] + bsum[32 + aj];
            float vo = gr[48 + aj] + bsum[48 + aj];
            if (LAYER == 1) {
                float xv = xs[ab];
                vi = fmaf(xv, wih1s[     aj], vi);
                vf = fmaf(xv, wih1s[16 + aj], vf);
                vg = fmaf(xv, wih1s[32 + aj], vg);
                vo = fmaf(xv, wih1s[48 + aj], vo);
            } else {
                const float* xp = xp2_s + (t & 1) * 2176 + ab * 68;
                vi += xp[      aj];
                vf += xp[16 + aj];
                vg += xp[32 + aj];
                vo += xp[48 + aj];
            }
            float iv = sig_(vi), fv = sig_(vf), gv = tanh_(vg), ov = sig_(vo);
            float cn = fmaf(fv, c_s[tid], iv * gv);
            c_s[tid] = cn;
            float hn = ov * tanh_(cn);
            size_t hoff = ((size_t)c * Hv + jbase + aj) * Bv + ab;   // coalesced
            g_hbuf[(size_t)(t & 1) * (Cv * Hv * Bv) + hoff] = hn;
            if (LAYER == 1)
                g_h1[(((size_t)t * Cv + c) * Hv + jbase + aj) * Bv + ab] = hn;
            else
                part0[aj * 33 + ab] = hn * wlin16[aj];   // head staging (part0 dead here)
        }

        chan_barrier(c, lsense);

        // ---- reload full h[t] for this channel into h_s[k][b] ----
        {
            const float4* src = (const float4*)(g_hbuf + (size_t)(t & 1) * (Cv * Hv * Bv)
                                                        + (size_t)c * Hv * Bv);
            float4* dst = (float4*)h_s;
            #pragma unroll
            for (int i = 0; i < 4; ++i)
                dst[tid + i * 512] = __ldcg(src + tid + i * 512);
        }

        // ---- head partial: one warp sums this CTA's 16 j-lanes, stores off-path ----
        if (LAYER == 2 && tid < 32) {
            float s = 0.0f;
            #pragma unroll
            for (int j = 0; j < 16; ++j) s += part0[j * 33 + tid];
            g_opart[(((size_t)t * Cv + c) * 16 + rank) * Bv + tid] = s;
        }
        // loop-top __syncthreads orders h_s reload + part0 reads before next compute
    }
}

// ---------------- epilogue: out[b][t][c] = blin[c] + sum_rank opart ----------------
__global__ __launch_bounds__(256)
void head_kernel(const float* __restrict__ blin, float* __restrict__ out)
{
    int i  = blockIdx.x * 256 + threadIdx.x;
    int b  = i & 31;
    int tc = i >> 5;
    int c  = tc & (Cv - 1);
    int t  = tc >> 3;
    const float* p = g_opart + (size_t)tc * 16 * Bv + b;
    float s = __ldg(&blin[c]);
    #pragma unroll
    for (int r = 0; r < 16; ++r) s += p[r * Bv];
    out[(size_t)b * Tv * Cv + t * Cv + c] = s;
}

// ---------------- launch ----------------
extern "C" void kernel_launch(void* const* d_in, const int* in_sizes, int n_in,
                              void* d_out, int out_size)
{
    const float* x    = (const float*)d_in[0];
    const float* Wih1 = (const float*)d_in[1];
    const float* Whh1 = (const float*)d_in[2];
    const float* bih1 = (const float*)d_in[3];
    const float* bhh1 = (const float*)d_in[4];
    const float* Wih2 = (const float*)d_in[5];
    const float* Whh2 = (const float*)d_in[6];
    const float* bih2 = (const float*)d_in[7];
    const float* bhh2 = (const float*)d_in[8];
    const float* Wlin = (const float*)d_in[9];
    const float* blin = (const float*)d_in[10];
    float* out = (float*)d_out;

    (void)in_sizes; (void)n_in; (void)out_size;

    cudaFuncSetAttribute(lstm_kernel<1>, cudaFuncAttributeMaxDynamicSharedMemorySize, SM_BYTES);
    cudaFuncSetAttribute(lstm_kernel<2>, cudaFuncAttributeMaxDynamicSharedMemorySize, SM_BYTES);
    cudaFuncSetAttribute(xp2_kernel, cudaFuncAttributeMaxDynamicSharedMemorySize, XP2_SM_BYTES);

    lstm_kernel<1><<<128, 512, SM_BYTES>>>(x, Wih1, Whh1, bih1, bhh1, nullptr);
    xp2_kernel<<<dim3(16, 8, 128), 512, XP2_SM_BYTES>>>(Wih2);
    lstm_kernel<2><<<128, 512, SM_BYTES>>>(nullptr, nullptr, Whh2, bih2, bhh2, Wlin);
    head_kernel<<<512, 256>>>(blin, out);
}

// round 15
// speedup vs baseline: 1.1240x; 1.1240x over previous
#include <cuda_runtime.h>
#include <cstddef>
#include <cstring>

#define Bv 32
#define Tv 512
#define Cv 8
#define Hv 256
#define Gv 1024

// ---------------- scratch (device globals: allocation-free) ----------------
__device__ float g_h1[(size_t)Tv * Cv * Hv * Bv];    // layer1 hidden, [T][C][H][B]
__device__ float g_hbuf[2 * Cv * Hv * Bv];           // h exchange, [2][C][H][B]
__device__ float g_opart[(size_t)Tv * Cv * 16 * Bv]; // head partials [T][C][rank][B]
__device__ unsigned g_cnt[Cv];                       // barrier counters (zero-init)
__device__ unsigned g_sense[Cv];                     // barrier sense (zero-init)

// ---------------- math helpers ----------------
__device__ __forceinline__ float sig_(float x) {
    return __fdividef(1.0f, 1.0f + __expf(-x));
}
__device__ __forceinline__ float tanh_(float x) {
    float ax = fabsf(x);
    float e  = __expf(-2.0f * ax);
    float t  = __fdividef(1.0f - e, 1.0f + e);
    return copysignf(t, x);
}
__device__ __forceinline__ float2 u2f(unsigned long long u) {
    float2 f; memcpy(&f, &u, 8); return f;
}

// packed fp32x2 FMA (FFMA2) and operand duplication
#define FMA2(acc, h, w) asm("fma.rn.f32x2 %0, %1, %2, %0;" : "+l"(acc) : "l"(h), "l"(w))
#define PACK2(d, s)     asm("mov.b64 %0, {%1, %1};" : "=l"(d) : "f"(s))

// cp.async helpers
__device__ __forceinline__ unsigned smem_u32(const void* p) {
    unsigned r;
    asm("{ .reg .u64 t; cvta.to.shared.u64 t, %1; cvt.u32.u64 %0, t; }" : "=r"(r) : "l"(p));
    return r;
}
__device__ __forceinline__ void cp16(unsigned s, const void* g) {
    asm volatile("cp.async.cg.shared.global [%0], [%1], 16;" :: "r"(s), "l"(g));
}
#define CP_COMMIT() asm volatile("cp.async.commit_group;" ::: "memory")
#define CP_WAIT0()  asm volatile("cp.async.wait_group 0;" ::: "memory")

// per-channel sense-reversing barrier (R7/R13-proven, BYTE-IDENTICAL) — used by L1
__device__ __forceinline__ void chan_barrier(int c, unsigned &lsense) {
    __syncthreads();
    if (threadIdx.x == 0) {
        __threadfence();
        unsigned a = atomicAdd(&g_cnt[c], 1u);
        if (a == 15u) {
            *(volatile unsigned*)&g_cnt[c] = 0u;
            __threadfence();
            *(volatile unsigned*)&g_sense[c] = lsense ^ 1u;
        } else {
            while (*(volatile unsigned*)&g_sense[c] == lsense) { __nanosleep(20); }
            __threadfence();
        }
    }
    lsense ^= 1u;
    __syncthreads();
}

// ---------------- smem layout (floats) — R13-identical ----------------
#define GSTR 66
#define SM_FLOATS (16384 + 16384 + 8192 + 8192 + 3 * 2112 + 512 + 64 + 64 + 32 + 16)
#define SM_BYTES  (SM_FLOATS * 4)

template <int LAYER>
__global__ __launch_bounds__(512, 1)
void lstm_kernel(const float* __restrict__ x,
                 const float* __restrict__ Wih,   // L1: [C][G][1]; L2: [C][G][H]
                 const float* __restrict__ Whh,   // [C][G][H]
                 const float* __restrict__ bih,   // [C][G]
                 const float* __restrict__ bhh,   // [C][G]
                 const float* __restrict__ Wlin)  // [C][H]  (L2)
{
    extern __shared__ float sm[];
    float* Whh_s  = sm;
    float* Wih_s  = Whh_s + 16384;
    float* h_s    = Wih_s + 16384;
    float* h1_s   = h_s   + 8192;
    float* gsm    = h1_s  + 8192;
    float* part0  = gsm   + Bv * GSTR;
    float* part1  = part0 + Bv * GSTR;
    float* c_s    = part1 + Bv * GSTR;
    float* bsum   = c_s   + 512;
    float* wih1s  = bsum  + 64;
    float* xs     = wih1s + 64;
    float* wlin16 = xs    + 32;

    const int tid   = threadIdx.x;
    const int c     = blockIdx.x >> 4;
    const int rank  = blockIdx.x & 15;
    const int jbase = rank << 4;

    // compute decomposition (R7-proven): warp = 32 row-pairs, fixed (oct, kq)
    const int rp  = tid & 31;
    const int oct = (tid >> 5) & 3;
    const int kq  = tid >> 7;

    // activation decomposition (coalesced global stores)
    const int ab = tid & 31;
    const int aj = tid >> 5;

    // ---- init: weights k-major, biases, zero state ----
    for (int idx = tid; idx < 64 * Hv; idx += 512) {
        int k  = idx >> 6;
        int r  = idx & 63;
        int g  = r >> 4;
        int jl = r & 15;
        size_t grow = (size_t)c * Gv + g * Hv + (jbase + jl);
        Whh_s[k * 64 + r] = Whh[grow * Hv + k];
        if (LAYER == 2)
            Wih_s[k * 64 + r] = Wih[grow * Hv + k];
    }
    if (tid < 64) {
        int g = tid >> 4, jl = tid & 15;
        size_t gi = (size_t)c * Gv + g * Hv + (jbase + jl);
        bsum[tid] = bih[gi] + bhh[gi];
        if (LAYER == 1) wih1s[tid] = Wih[gi];
    }
    if (LAYER == 2 && tid < 16) wlin16[tid] = Wlin[c * Hv + jbase + tid];
    for (int i = tid; i < Hv * Bv; i += 512) h_s[i] = 0.0f;
    c_s[tid] = 0.0f;
    __syncthreads();

    const unsigned h1s_addr = smem_u32(h1_s) + (unsigned)tid * 16u;

    unsigned long long Bk[8];
    #pragma unroll
    for (int i = 0; i < 8; ++i) Bk[i] = 0ull;

    // ---- pre-loop: stage inputs for step 0; L2 also precomputes ih(h1[0]) ----
    float xr = 0.0f;
    if (LAYER == 2) {
        const float* src = g_h1 + ((size_t)0 * Cv + c) * (Hv * Bv) + tid * 4;
        #pragma unroll
        for (int i = 0; i < 4; ++i) cp16(h1s_addr + i * 512u * 16u, src + i * 512 * 4);
        CP_COMMIT(); CP_WAIT0();
        __syncthreads();
        // ih matvec for t=0 (clone of proven inner loop)
        const float* wi  = Wih_s + kq * 64 * 64 + 2 * rp;
        const float* ppp = h1_s  + kq * 64 * 32 + oct * 8;
        #pragma unroll 4
        for (int kk = 0; kk < 64; ++kk) {
            float2 vv = *(const float2*)wi;  wi += 64;
            unsigned long long v0, v1;
            PACK2(v0, vv.x); PACK2(v1, vv.y);
            ulonglong2 pa = *(const ulonglong2*)ppp;
            ulonglong2 pb = *(const ulonglong2*)(ppp + 4);  ppp += 32;
            FMA2(Bk[0], pa.x, v0); FMA2(Bk[1], pa.y, v0);
            FMA2(Bk[2], pb.x, v0); FMA2(Bk[3], pb.y, v0);
            FMA2(Bk[4], pa.x, v1); FMA2(Bk[5], pa.y, v1);
            FMA2(Bk[6], pb.x, v1); FMA2(Bk[7], pb.y, v1);
        }
        __syncthreads();   // all ih(0) reads done before h1_s is overwritten
    } else {
        if (tid < Bv) xr = __ldg(&x[(size_t)tid * Tv * Cv + c]);
    }

    unsigned lsense = 0;

    for (int t = 0; t < Tv; ++t) {
        // ---- L2: issue prefetch of h1[t+1] (h1_s free: ih(t) consumed) ----
        if (LAYER == 2 && t + 1 < Tv) {
            const float* src = g_h1 + ((size_t)(t + 1) * Cv + c) * (Hv * Bv) + tid * 4;
            #pragma unroll
            for (int i = 0; i < 4; ++i) cp16(h1s_addr + i * 512u * 16u, src + i * 512 * 4);
            CP_COMMIT();
        }
        if (LAYER == 1) { if (tid < Bv) xs[tid] = xr; }
        __syncthreads();   // h_s reload (prev step) + staged inputs visible

        // ---- hh mat-vec: rows {2rp,2rp+1} x batches oct*8..+7 over k-quarter ----
        unsigned long long A[8];
        #pragma unroll
        for (int i = 0; i < 8; ++i) A[i] = 0ull;
        {
            const float* wh  = Whh_s + kq * 64 * 64 + 2 * rp;
            const float* hpp = h_s   + kq * 64 * 32 + oct * 8;

            #pragma unroll 4
            for (int kk = 0; kk < 64; ++kk) {
                float2 wv = *(const float2*)wh;  wh += 64;
                unsigned long long w0, w1;
                PACK2(w0, wv.x); PACK2(w1, wv.y);
                ulonglong2 ha = *(const ulonglong2*)hpp;
                ulonglong2 hb = *(const ulonglong2*)(hpp + 4);  hpp += 32;
                FMA2(A[0], ha.x, w0); FMA2(A[1], ha.y, w0);
                FMA2(A[2], hb.x, w0); FMA2(A[3], hb.y, w0);
                FMA2(A[4], ha.x, w1); FMA2(A[5], ha.y, w1);
                FMA2(A[6], hb.x, w1); FMA2(A[7], hb.y, w1);
            }
        }
        // merge hh + carried ih accumulators
        float2 R[8];
        #pragma unroll
        for (int i = 0; i < 8; ++i) {
            float2 fa = u2f(A[i]);
            if (LAYER == 2) { float2 fb = u2f(Bk[i]); fa.x += fb.x; fa.y += fb.y; }
            R[i] = fa;
        }

        // ---- cross-kq reduction: kq 0->gsm, 2->part0, 3->part1; kq1 combines ----
        {
            float* dst = (kq == 0) ? gsm : (kq == 2) ? part0 : (kq == 3) ? part1 : (float*)0;
            if (dst) {
                #pragma unroll
                for (int p = 0; p < 4; ++p) {
                    int b = oct * 8 + 2 * p;
                    *(float2*)(dst + b * GSTR + 2 * rp)       = make_float2(R[p].x, R[4 + p].x);
                    *(float2*)(dst + (b + 1) * GSTR + 2 * rp) = make_float2(R[p].y, R[4 + p].y);
                }
            }
        }
        __syncthreads();   // sync1

        if (LAYER == 1) {
            if (tid < Bv && t + 1 < Tv)
                xr = __ldg(&x[(size_t)tid * Tv * Cv + (t + 1) * Cv + c]);
        }

        if (kq == 1) {
            #pragma unroll
            for (int p = 0; p < 4; ++p) {
                int b = oct * 8 + 2 * p;
                float2* g0 = (float2*)(gsm + b * GSTR + 2 * rp);
                float2* g1 = (float2*)(gsm + (b + 1) * GSTR + 2 * rp);
                float2 p00 = *(float2*)(part0 + b * GSTR + 2 * rp);
                float2 p01 = *(float2*)(part0 + (b + 1) * GSTR + 2 * rp);
                float2 p10 = *(float2*)(part1 + b * GSTR + 2 * rp);
                float2 p11 = *(float2*)(part1 + (b + 1) * GSTR + 2 * rp);
                float2 a = *g0, bb = *g1;
                a.x  += p00.x + p10.x + R[p].x;
                a.y  += p00.y + p10.y + R[4 + p].x;
                bb.x += p01.x + p11.x + R[p].y;
                bb.y += p01.y + p11.y + R[4 + p].y;
                *g0 = a; *g1 = bb;
            }
        }
        __syncthreads();   // sync2: gsm final (part0/part1 dead until next sync1)

        // ---- activations + state update: thread -> (b = lane, j = warp) ----
        {
            const float* gr = gsm + ab * GSTR;
            float vi = gr[      aj] + bsum[      aj];
            float vf = gr[16 + aj] + bsum[16 + aj];
            float vg = gr[32 + aj] + bsum[32 + aj];
            float vo = gr[48 + aj] + bsum[48 + aj];
            if (LAYER == 1) {
                float xv = xs[ab];
                vi = fmaf(xv, wih1s[     aj], vi);
                vf = fmaf(xv, wih1s[16 + aj], vf);
                vg = fmaf(xv, wih1s[32 + aj], vg);
                vo = fmaf(xv, wih1s[48 + aj], vo);
            }
            float iv = sig_(vi), fv = sig_(vf), gv = tanh_(vg), ov = sig_(vo);
            float cn = fmaf(fv, c_s[tid], iv * gv);
            c_s[tid] = cn;
            float hn = ov * tanh_(cn);
            size_t hoff = ((size_t)c * Hv + jbase + aj) * Bv + ab;   // coalesced
            g_hbuf[(size_t)(t & 1) * (Cv * Hv * Bv) + hoff] = hn;
            if (LAYER == 1)
                g_h1[(((size_t)t * Cv + c) * Hv + jbase + aj) * Bv + ab] = hn;
            else
                part0[aj * 33 + ab] = hn * wlin16[aj];   // head staging (part0 dead here)
        }

        // ---- channel barrier; L2 hides ih(t+1) inside the wait window ----
        if (LAYER == 1) {
            chan_barrier(c, lsense);
        } else {
            __syncthreads();                       // entry: hn stores issued block-wide
            bool leader = false;
            if (tid == 0) {
                __threadfence();                   // release
                unsigned a = atomicAdd(&g_cnt[c], 1u);
                if (a == 15u) {
                    *(volatile unsigned*)&g_cnt[c] = 0u;
                    __threadfence();
                    *(volatile unsigned*)&g_sense[c] = lsense ^ 1u;
                    leader = true;
                }
            }
            CP_WAIT0();                            // this thread's h1[t+1] chunks landed
            __syncthreads();                       // all chunks visible
            if (t + 1 < Tv) {                      // ih matvec for t+1 (hidden work)
                #pragma unroll
                for (int i = 0; i < 8; ++i) Bk[i] = 0ull;
                const float* wi  = Wih_s + kq * 64 * 64 + 2 * rp;
                const float* ppp = h1_s  + kq * 64 * 32 + oct * 8;
                #pragma unroll 4
                for (int kk = 0; kk < 64; ++kk) {
                    float2 vv = *(const float2*)wi;  wi += 64;
                    unsigned long long v0, v1;
                    PACK2(v0, vv.x); PACK2(v1, vv.y);
                    ulonglong2 pa = *(const ulonglong2*)ppp;
                    ulonglong2 pb = *(const ulonglong2*)(ppp + 4);  ppp += 32;
                    FMA2(Bk[0], pa.x, v0); FMA2(Bk[1], pa.y, v0);
                    FMA2(Bk[2], pb.x, v0); FMA2(Bk[3], pb.y, v0);
                    FMA2(Bk[4], pa.x, v1); FMA2(Bk[5], pa.y, v1);
                    FMA2(Bk[6], pb.x, v1); FMA2(Bk[7], pb.y, v1);
                }
            }
            if (tid == 0 && !leader) {
                while (*(volatile unsigned*)&g_sense[c] == lsense) { __nanosleep(20); }
                __threadfence();                   // acquire
            }
            lsense ^= 1u;
            __syncthreads();                       // exit
        }

        // ---- reload full h[t] for this channel into h_s[k][b] ----
        {
            const float4* src = (const float4*)(g_hbuf + (size_t)(t & 1) * (Cv * Hv * Bv)
                                                        + (size_t)c * Hv * Bv);
            float4* dst = (float4*)h_s;
            #pragma unroll
            for (int i = 0; i < 4; ++i)
                dst[tid + i * 512] = __ldcg(src + tid + i * 512);
        }

        // ---- head partial: one warp sums this CTA's 16 j-lanes, stores off-path ----
        if (LAYER == 2 && tid < 32) {
            float s = 0.0f;
            #pragma unroll
            for (int j = 0; j < 16; ++j) s += part0[j * 33 + tid];
            g_opart[(((size_t)t * Cv + c) * 16 + rank) * Bv + tid] = s;
        }
        // loop-top __syncthreads orders h_s reload + part0 reads before next compute
    }
}

// ---------------- epilogue: out[b][t][c] = blin[c] + sum_rank opart ----------------
__global__ __launch_bounds__(256)
void head_kernel(const float* __restrict__ blin, float* __restrict__ out)
{
    int i  = blockIdx.x * 256 + threadIdx.x;
    int b  = i & 31;
    int tc = i >> 5;
    int c  = tc & (Cv - 1);
    int t  = tc >> 3;
    const float* p = g_opart + (size_t)tc * 16 * Bv + b;
    float s = __ldg(&blin[c]);
    #pragma unroll
    for (int r = 0; r < 16; ++r) s += p[r * Bv];
    out[(size_t)b * Tv * Cv + t * Cv + c] = s;
}

// ---------------- launch ----------------
extern "C" void kernel_launch(void* const* d_in, const int* in_sizes, int n_in,
                              void* d_out, int out_size)
{
    const float* x    = (const float*)d_in[0];
    const float* Wih1 = (const float*)d_in[1];
    const float* Whh1 = (const float*)d_in[2];
    const float* bih1 = (const float*)d_in[3];
    const float* bhh1 = (const float*)d_in[4];
    const float* Wih2 = (const float*)d_in[5];
    const float* Whh2 = (const float*)d_in[6];
    const float* bih2 = (const float*)d_in[7];
    const float* bhh2 = (const float*)d_in[8];
    const float* Wlin = (const float*)d_in[9];
    const float* blin = (const float*)d_in[10];
    float* out = (float*)d_out;

    (void)in_sizes; (void)n_in; (void)out_size;

    cudaFuncSetAttribute(lstm_kernel<1>, cudaFuncAttributeMaxDynamicSharedMemorySize, SM_BYTES);
    cudaFuncSetAttribute(lstm_kernel<2>, cudaFuncAttributeMaxDynamicSharedMemorySize, SM_BYTES);

    lstm_kernel<1><<<128, 512, SM_BYTES>>>(x, Wih1, Whh1, bih1, bhh1, nullptr);
    lstm_kernel<2><<<128, 512, SM_BYTES>>>(nullptr, Wih2, Whh2, bih2, bhh2, Wlin);
    head_kernel<<<512, 256>>>(blin, out);
}

// round 16
// speedup vs baseline: 1.2639x; 1.1244x over previous
#include <cuda_runtime.h>
#include <cstddef>
#include <cstring>

#define Bv 32
#define Tv 512
#define Cv 8
#define Hv 256
#define Gv 1024

// ---------------- scratch (device globals: allocation-free) ----------------
__device__ float g_h1[(size_t)Tv * Cv * Hv * Bv];    // layer1 hidden, [T][C][H][B]
__device__ float g_hbuf[2 * Cv * Hv * Bv];           // h exchange, [2][C][H][B]
__device__ float g_opart[(size_t)Tv * Cv * 16 * Bv]; // head partials [T][C][rank][B]
__device__ unsigned g_cnt[Cv];                       // barrier counters (zero-init)
__device__ unsigned g_sense[Cv];                     // barrier sense (zero-init)

// ---------------- math helpers ----------------
__device__ __forceinline__ float sig_(float x) {
    return __fdividef(1.0f, 1.0f + __expf(-x));
}
__device__ __forceinline__ float tanh_(float x) {
    float ax = fabsf(x);
    float e  = __expf(-2.0f * ax);
    float t  = __fdividef(1.0f - e, 1.0f + e);
    return copysignf(t, x);
}
__device__ __forceinline__ float2 u2f(unsigned long long u) {
    float2 f; memcpy(&f, &u, 8); return f;
}

// packed fp32x2 FMA (FFMA2) and operand duplication
#define FMA2(acc, h, w) asm("fma.rn.f32x2 %0, %1, %2, %0;" : "+l"(acc) : "l"(h), "l"(w))
#define PACK2(d, s)     asm("mov.b64 %0, {%1, %1};" : "=l"(d) : "f"(s))

// cp.async helpers
__device__ __forceinline__ unsigned smem_u32(const void* p) {
    unsigned r;
    asm("{ .reg .u64 t; cvta.to.shared.u64 t, %1; cvt.u32.u64 %0, t; }" : "=r"(r) : "l"(p));
    return r;
}
__device__ __forceinline__ void cp16(unsigned s, const void* g) {
    asm volatile("cp.async.cg.shared.global [%0], [%1], 16;" :: "r"(s), "l"(g));
}
#define CP_COMMIT() asm volatile("cp.async.commit_group;" ::: "memory")
#define CP_WAIT0()  asm volatile("cp.async.wait_group 0;" ::: "memory")

// per-channel sense-reversing barrier (R7/R13-proven, BYTE-IDENTICAL) — used by L1
__device__ __forceinline__ void chan_barrier(int c, unsigned &lsense) {
    __syncthreads();
    if (threadIdx.x == 0) {
        __threadfence();
        unsigned a = atomicAdd(&g_cnt[c], 1u);
        if (a == 15u) {
            *(volatile unsigned*)&g_cnt[c] = 0u;
            __threadfence();
            *(volatile unsigned*)&g_sense[c] = lsense ^ 1u;
        } else {
            while (*(volatile unsigned*)&g_sense[c] == lsense) { __nanosleep(20); }
            __threadfence();
        }
    }
    lsense ^= 1u;
    __syncthreads();
}

// ---------------- smem layout (floats) — R15-identical ----------------
#define GSTR 66
#define SM_FLOATS (16384 + 16384 + 8192 + 8192 + 3 * 2112 + 512 + 64 + 64 + 32 + 16)
#define SM_BYTES  (SM_FLOATS * 4)

// New-tiling matvec body: 4 rows (4rq..4rq+3) x 4 batches (bb4..bb4+3) over one
// k-quarter. acc[p] (p=0..3): f32x2 = rows(4rq,4rq+1) for batch bb4+p;
// acc[4+p]: rows(4rq+2,4rq+3). W_base/H_base point at the kq-quarter.
__device__ __forceinline__ void matvec4x4(unsigned long long* acc,
                                          const float* __restrict__ Wq,
                                          const float* __restrict__ Hq,
                                          int rq4, int bb4)
{
    const float* wh = Wq + rq4;
    const float* hp = Hq + bb4;
    #pragma unroll 4
    for (int kk = 0; kk < 64; ++kk) {
        ulonglong2 wl = *(const ulonglong2*)wh;  wh += 64;   // rows rq4..rq4+3
        float4 hv = *(const float4*)hp;          hp += 32;   // batches bb4..bb4+3
        unsigned long long hd0, hd1, hd2, hd3;
        PACK2(hd0, hv.x); PACK2(hd1, hv.y); PACK2(hd2, hv.z); PACK2(hd3, hv.w);
        FMA2(acc[0], hd0, wl.x); FMA2(acc[1], hd1, wl.x);
        FMA2(acc[2], hd2, wl.x); FMA2(acc[3], hd3, wl.x);
        FMA2(acc[4], hd0, wl.y); FMA2(acc[5], hd1, wl.y);
        FMA2(acc[6], hd2, wl.y); FMA2(acc[7], hd3, wl.y);
    }
}

template <int LAYER>
__global__ __launch_bounds__(512, 1)
void lstm_kernel(const float* __restrict__ x,
                 const float* __restrict__ Wih,   // L1: [C][G][1]; L2: [C][G][H]
                 const float* __restrict__ Whh,   // [C][G][H]
                 const float* __restrict__ bih,   // [C][G]
                 const float* __restrict__ bhh,   // [C][G]
                 const float* __restrict__ Wlin)  // [C][H]  (L2)
{
    extern __shared__ float sm[];
    float* Whh_s  = sm;
    float* Wih_s  = Whh_s + 16384;
    float* h_s    = Wih_s + 16384;
    float* h1_s   = h_s   + 8192;
    float* gsm    = h1_s  + 8192;
    float* part0  = gsm   + Bv * GSTR;
    float* part1  = part0 + Bv * GSTR;
    float* c_s    = part1 + Bv * GSTR;
    float* bsum   = c_s   + 512;
    float* wih1s  = bsum  + 64;
    float* xs     = wih1s + 64;
    float* wlin16 = xs    + 32;

    const int tid   = threadIdx.x;
    const int c     = blockIdx.x >> 4;
    const int rank  = blockIdx.x & 15;
    const int jbase = rank << 4;

    // NEW compute decomposition: lane = (rq, ol); warp = (op, kq)
    const int lane = tid & 31;
    const int warp = tid >> 5;
    const int rq   = lane >> 1;          // row-quad index: rows 4rq..4rq+3
    const int ol   = lane & 1;
    const int kq   = warp & 3;           // k-quarter
    const int op   = warp >> 2;          // oct-pair
    const int oct  = op * 2 + ol;        // batch quad index
    const int rq4  = rq << 2;            // first local gate-row
    const int bb4  = oct << 2;           // first batch

    // activation decomposition (coalesced global stores)
    const int ab = tid & 31;
    const int aj = tid >> 5;

    // ---- init: weights k-major, biases, zero state ----
    for (int idx = tid; idx < 64 * Hv; idx += 512) {
        int k  = idx >> 6;
        int r  = idx & 63;
        int g  = r >> 4;
        int jl = r & 15;
        size_t grow = (size_t)c * Gv + g * Hv + (jbase + jl);
        Whh_s[k * 64 + r] = Whh[grow * Hv + k];
        if (LAYER == 2)
            Wih_s[k * 64 + r] = Wih[grow * Hv + k];
    }
    if (tid < 64) {
        int g = tid >> 4, jl = tid & 15;
        size_t gi = (size_t)c * Gv + g * Hv + (jbase + jl);
        bsum[tid] = bih[gi] + bhh[gi];
        if (LAYER == 1) wih1s[tid] = Wih[gi];
    }
    if (LAYER == 2 && tid < 16) wlin16[tid] = Wlin[c * Hv + jbase + tid];
    for (int i = tid; i < Hv * Bv; i += 512) h_s[i] = 0.0f;
    c_s[tid] = 0.0f;
    __syncthreads();

    const unsigned h1s_addr = smem_u32(h1_s) + (unsigned)tid * 16u;

    unsigned long long Bk[8];
    #pragma unroll
    for (int i = 0; i < 8; ++i) Bk[i] = 0ull;

    // ---- pre-loop: stage inputs for step 0; L2 precomputes ih(h1[0]) ----
    float xr = 0.0f;
    if (LAYER == 2) {
        const float* src = g_h1 + ((size_t)0 * Cv + c) * (Hv * Bv) + tid * 4;
        #pragma unroll
        for (int i = 0; i < 4; ++i) cp16(h1s_addr + i * 512u * 16u, src + i * 512 * 4);
        CP_COMMIT(); CP_WAIT0();
        __syncthreads();
        matvec4x4(Bk, Wih_s + kq * 4096, h1_s + kq * 2048, rq4, bb4);
        __syncthreads();   // all ih(0) reads done before h1_s is overwritten
    } else {
        if (tid < Bv) xr = __ldg(&x[(size_t)tid * Tv * Cv + c]);
    }

    unsigned lsense = 0;

    for (int t = 0; t < Tv; ++t) {
        // ---- L2: issue prefetch of h1[t+1] (h1_s free: ih(t) consumed) ----
        if (LAYER == 2 && t + 1 < Tv) {
            const float* src = g_h1 + ((size_t)(t + 1) * Cv + c) * (Hv * Bv) + tid * 4;
            #pragma unroll
            for (int i = 0; i < 4; ++i) cp16(h1s_addr + i * 512u * 16u, src + i * 512 * 4);
            CP_COMMIT();
        }
        if (LAYER == 1) { if (tid < Bv) xs[tid] = xr; }
        __syncthreads();   // h_s reload (prev step) + staged inputs visible

        // ---- hh mat-vec (new tiling) ----
        unsigned long long A[8];
        #pragma unroll
        for (int i = 0; i < 8; ++i) A[i] = 0ull;
        matvec4x4(A, Whh_s + kq * 4096, h_s + kq * 2048, rq4, bb4);

        // merge hh + carried ih accumulators (layouts identical)
        float2 R[8];
        #pragma unroll
        for (int i = 0; i < 8; ++i) {
            float2 fa = u2f(A[i]);
            if (LAYER == 2) { float2 fb = u2f(Bk[i]); fa.x += fb.x; fa.y += fb.y; }
            R[i] = fa;
        }

        // ---- cross-kq reduction: kq 0->gsm, 2->part0, 3->part1; kq1 combines ----
        {
            float* dst = (kq == 0) ? gsm : (kq == 2) ? part0 : (kq == 3) ? part1 : (float*)0;
            if (dst) {
                #pragma unroll
                for (int p = 0; p < 4; ++p) {
                    int b = bb4 + p;
                    *(float2*)(dst + b * GSTR + rq4)     = R[p];       // rows rq4, rq4+1
                    *(float2*)(dst + b * GSTR + rq4 + 2) = R[4 + p];   // rows rq4+2, rq4+3
                }
            }
        }
        __syncthreads();   // sync1

        if (LAYER == 1) {
            if (tid < Bv && t + 1 < Tv)
                xr = __ldg(&x[(size_t)tid * Tv * Cv + (t + 1) * Cv + c]);
        }

        if (kq == 1) {
            #pragma unroll
            for (int p = 0; p < 4; ++p) {
                int b = bb4 + p;
                float2* g0 = (float2*)(gsm + b * GSTR + rq4);
                float2* g1 = (float2*)(gsm + b * GSTR + rq4 + 2);
                float2 p00 = *(float2*)(part0 + b * GSTR + rq4);
                float2 p01 = *(float2*)(part0 + b * GSTR + rq4 + 2);
                float2 p10 = *(float2*)(part1 + b * GSTR + rq4);
                float2 p11 = *(float2*)(part1 + b * GSTR + rq4 + 2);
                float2 a = *g0, bb = *g1;
                a.x  += p00.x + p10.x + R[p].x;
                a.y  += p00.y + p10.y + R[p].y;
                bb.x += p01.x + p11.x + R[4 + p].x;
                bb.y += p01.y + p11.y + R[4 + p].y;
                *g0 = a; *g1 = bb;
            }
        }
        __syncthreads();   // sync2: gsm final

        // ---- activations + state update: thread -> (b = lane, j = warp) ----
        {
            const float* gr = gsm + ab * GSTR;
            float vi = gr[      aj] + bsum[      aj];
            float vf = gr[16 + aj] + bsum[16 + aj];
            float vg = gr[32 + aj] + bsum[32 + aj];
            float vo = gr[48 + aj] + bsum[48 + aj];
            if (LAYER == 1) {
                float xv = xs[ab];
                vi = fmaf(xv, wih1s[     aj], vi);
                vf = fmaf(xv, wih1s[16 + aj], vf);
                vg = fmaf(xv, wih1s[32 + aj], vg);
                vo = fmaf(xv, wih1s[48 + aj], vo);
            }
            float iv = sig_(vi), fv = sig_(vf), gv = tanh_(vg), ov = sig_(vo);
            float cn = fmaf(fv, c_s[tid], iv * gv);
            c_s[tid] = cn;
            float hn = ov * tanh_(cn);
            size_t hoff = ((size_t)c * Hv + jbase + aj) * Bv + ab;   // coalesced
            g_hbuf[(size_t)(t & 1) * (Cv * Hv * Bv) + hoff] = hn;
            if (LAYER == 1)
                g_h1[(((size_t)t * Cv + c) * Hv + jbase + aj) * Bv + ab] = hn;
            else
                part0[aj * 33 + ab] = hn * wlin16[aj];   // head staging (part0 dead here)
        }

        // ---- channel barrier; L2 hides ih(t+1) inside the wait window ----
        if (LAYER == 1) {
            chan_barrier(c, lsense);
        } else {
            __syncthreads();                       // entry: hn stores issued block-wide
            bool leader = false;
            if (tid == 0) {
                __threadfence();                   // release
                unsigned a = atomicAdd(&g_cnt[c], 1u);
                if (a == 15u) {
                    *(volatile unsigned*)&g_cnt[c] = 0u;
                    __threadfence();
                    *(volatile unsigned*)&g_sense[c] = lsense ^ 1u;
                    leader = true;
                }
            }
            CP_WAIT0();                            // h1[t+1] chunks landed
            __syncthreads();                       // all chunks visible
            if (t + 1 < Tv) {                      // ih matvec for t+1 (hidden work)
                #pragma unroll
                for (int i = 0; i < 8; ++i) Bk[i] = 0ull;
                matvec4x4(Bk, Wih_s + kq * 4096, h1_s + kq * 2048, rq4, bb4);
            }
            if (tid == 0 && !leader) {
                while (*(volatile unsigned*)&g_sense[c] == lsense) { __nanosleep(20); }
                __threadfence();                   // acquire
            }
            lsense ^= 1u;
            __syncthreads();                       // exit
        }

        // ---- reload full h[t] for this channel into h_s[k][b] ----
        {
            const float4* src = (const float4*)(g_hbuf + (size_t)(t & 1) * (Cv * Hv * Bv)
                                                        + (size_t)c * Hv * Bv);
            float4* dst = (float4*)h_s;
            #pragma unroll
            for (int i = 0; i < 4; ++i)
                dst[tid + i * 512] = __ldcg(src + tid + i * 512);
        }

        // ---- head partial: one warp sums this CTA's 16 j-lanes, stores off-path ----
        if (LAYER == 2 && tid < 32) {
            float s = 0.0f;
            #pragma unroll
            for (int j = 0; j < 16; ++j) s += part0[j * 33 + tid];
            g_opart[(((size_t)t * Cv + c) * 16 + rank) * Bv + tid] = s;
        }
        // loop-top __syncthreads orders h_s reload + part0 reads before next compute
    }
}

// ---------------- epilogue: out[b][t][c] = blin[c] + sum_rank opart ----------------
__global__ __launch_bounds__(256)
void head_kernel(const float* __restrict__ blin, float* __restrict__ out)
{
    int i  = blockIdx.x * 256 + threadIdx.x;
    int b  = i & 31;
    int tc = i >> 5;
    int c  = tc & (Cv - 1);
    int t  = tc >> 3;
    const float* p = g_opart + (size_t)tc * 16 * Bv + b;
    float s = __ldg(&blin[c]);
    #pragma unroll
    for (int r = 0; r < 16; ++r) s += p[r * Bv];
    out[(size_t)b * Tv * Cv + t * Cv + c] = s;
}

// ---------------- launch ----------------
extern "C" void kernel_launch(void* const* d_in, const int* in_sizes, int n_in,
                              void* d_out, int out_size)
{
    const float* x    = (const float*)d_in[0];
    const float* Wih1 = (const float*)d_in[1];
    const float* Whh1 = (const float*)d_in[2];
    const float* bih1 = (const float*)d_in[3];
    const float* bhh1 = (const float*)d_in[4];
    const float* Wih2 = (const float*)d_in[5];
    const float* Whh2 = (const float*)d_in[6];
    const float* bih2 = (const float*)d_in[7];
    const float* bhh2 = (const float*)d_in[8];
    const float* Wlin = (const float*)d_in[9];
    const float* blin = (const float*)d_in[10];
    float* out = (float*)d_out;

    (void)in_sizes; (void)n_in; (void)out_size;

    cudaFuncSetAttribute(lstm_kernel<1>, cudaFuncAttributeMaxDynamicSharedMemorySize, SM_BYTES);
    cudaFuncSetAttribute(lstm_kernel<2>, cudaFuncAttributeMaxDynamicSharedMemorySize, SM_BYTES);

    lstm_kernel<1><<<128, 512, SM_BYTES>>>(x, Wih1, Whh1, bih1, bhh1, nullptr);
    lstm_kernel<2><<<128, 512, SM_BYTES>>>(nullptr, Wih2, Whh2, bih2, bhh2, Wlin);
    head_kernel<<<512, 256>>>(blin, out);
}